// round 1
// baseline (speedup 1.0000x reference)
#include <cuda_runtime.h>
#include <cuda_bf16.h>
#include <cstdint>

// Problem dims (fixed per reference)
#define Bb 8
#define Ss 2048
#define Dd 512
#define Ii 2048
#define Mtot (Bb * Ss)          // 16384 rows
#define LN3 1.0986122886681098f

// Scratch: adaptive_alpha and drive, [B,S,I] each (134 MB each). Device globals
// are the sanctioned scratch mechanism (no allocations allowed).
__device__ float g_A[(size_t)Mtot * Ii];
__device__ float g_C[(size_t)Mtot * Ii];

// ---------------------------------------------------------------------------
// f32x2 helpers (FFMA2 path — only reachable via PTX, 2x fp32 throughput)
// ---------------------------------------------------------------------------
__device__ __forceinline__ unsigned long long ffma2(unsigned long long a,
                                                    unsigned long long b,
                                                    unsigned long long c) {
    unsigned long long d;
    asm("fma.rn.f32x2 %0, %1, %2, %3;" : "=l"(d) : "l"(a), "l"(b), "l"(c));
    return d;
}
__device__ __forceinline__ unsigned long long pack_dup(float a) {
    unsigned long long d;
    asm("mov.b64 %0, {%1, %2};" : "=l"(d) : "f"(a), "f"(a));
    return d;
}
__device__ __forceinline__ void unpack2(unsigned long long v, float& lo, float& hi) {
    asm("mov.b64 {%0, %1}, %2;" : "=f"(lo), "=f"(hi) : "l"(v));
}

__device__ __forceinline__ float sigmoidf(float x) {
    return 1.0f / (1.0f + __expf(-x));
}

// ---------------------------------------------------------------------------
// Fused dual-GEMM + gate epilogue.
// Block tile: 128 (M) x 64 (N), K-tile 32, 256 threads, each thread 8x4 output
// for BOTH Wa and Wi projections. Epilogue computes adaptive_alpha and drive.
// ---------------------------------------------------------------------------
__global__ __launch_bounds__(256, 2)
void gemm_gate_kernel(const float* __restrict__ x,
                      const float* __restrict__ Wa,
                      const float* __restrict__ ba,
                      const float* __restrict__ Wi,
                      const float* __restrict__ bi,
                      const float* __restrict__ gate) {
    __shared__ float sX[32 * 128];   // k-major: sX[k][m]
    __shared__ float sWa[32 * 64];   // k-major: sWa[k][n]
    __shared__ float sWi[32 * 64];

    const int tid = threadIdx.x;
    const int ty = tid >> 4;         // 0..15
    const int tx = tid & 15;         // 0..15
    const int m_sub = ty * 8;
    const int n_sub = tx * 4;

    const int M0 = blockIdx.y * 128;
    const int N0 = blockIdx.x * 64;

    // accumulators: [m][pair] for pa and pi, f32x2 packed (2 n per reg)
    unsigned long long accA[8][2];
    unsigned long long accI[8][2];
#pragma unroll
    for (int m = 0; m < 8; m++) {
        accA[m][0] = 0ULL; accA[m][1] = 0ULL;
        accI[m][0] = 0ULL; accI[m][1] = 0ULL;
    }

    const float* xg = x + (size_t)M0 * Dd;
    const float* wag = Wa + (size_t)N0 * Dd;
    const float* wig = Wi + (size_t)N0 * Dd;

    for (int k0 = 0; k0 < Dd; k0 += 32) {
        // ---- load x tile 128x32, transpose to k-major
#pragma unroll
        for (int t = tid; t < 1024; t += 256) {
            int r = t & 127;
            int g = t >> 7;              // 0..7 -> k group of 4
            float4 v = *(const float4*)(xg + (size_t)r * Dd + k0 + g * 4);
            sX[(g * 4 + 0) * 128 + r] = v.x;
            sX[(g * 4 + 1) * 128 + r] = v.y;
            sX[(g * 4 + 2) * 128 + r] = v.z;
            sX[(g * 4 + 3) * 128 + r] = v.w;
        }
        // ---- load Wa/Wi tiles 64x32, transpose to k-major
#pragma unroll
        for (int t = tid; t < 512; t += 256) {
            int r = t & 63;
            int g = t >> 6;              // 0..7
            float4 va = *(const float4*)(wag + (size_t)r * Dd + k0 + g * 4);
            sWa[(g * 4 + 0) * 64 + r] = va.x;
            sWa[(g * 4 + 1) * 64 + r] = va.y;
            sWa[(g * 4 + 2) * 64 + r] = va.z;
            sWa[(g * 4 + 3) * 64 + r] = va.w;
            float4 vi = *(const float4*)(wig + (size_t)r * Dd + k0 + g * 4);
            sWi[(g * 4 + 0) * 64 + r] = vi.x;
            sWi[(g * 4 + 1) * 64 + r] = vi.y;
            sWi[(g * 4 + 2) * 64 + r] = vi.z;
            sWi[(g * 4 + 3) * 64 + r] = vi.w;
        }
        __syncthreads();

#pragma unroll 8
        for (int kk = 0; kk < 32; kk++) {
            float4 a0 = *(const float4*)&sX[kk * 128 + m_sub];
            float4 a1 = *(const float4*)&sX[kk * 128 + m_sub + 4];
            ulonglong2 wa = *(const ulonglong2*)&sWa[kk * 64 + n_sub];
            ulonglong2 wi = *(const ulonglong2*)&sWi[kk * 64 + n_sub];
            unsigned long long ad[8];
            ad[0] = pack_dup(a0.x); ad[1] = pack_dup(a0.y);
            ad[2] = pack_dup(a0.z); ad[3] = pack_dup(a0.w);
            ad[4] = pack_dup(a1.x); ad[5] = pack_dup(a1.y);
            ad[6] = pack_dup(a1.z); ad[7] = pack_dup(a1.w);
#pragma unroll
            for (int m = 0; m < 8; m++) {
                accA[m][0] = ffma2(ad[m], wa.x, accA[m][0]);
                accA[m][1] = ffma2(ad[m], wa.y, accA[m][1]);
                accI[m][0] = ffma2(ad[m], wi.x, accI[m][0]);
                accI[m][1] = ffma2(ad[m], wi.y, accI[m][1]);
            }
        }
        __syncthreads();
    }

    // ---- epilogue: gate math, write a and c
    const int icol = N0 + n_sub;
    float bav[4], biv[4], gav[4];
    {
        float4 t;
        t = *(const float4*)(ba + icol);  bav[0]=t.x; bav[1]=t.y; bav[2]=t.z; bav[3]=t.w;
        t = *(const float4*)(bi + icol);  biv[0]=t.x; biv[1]=t.y; biv[2]=t.z; biv[3]=t.w;
        t = *(const float4*)(gate + icol); gav[0]=t.x; gav[1]=t.y; gav[2]=t.z; gav[3]=t.w;
    }

#pragma unroll
    for (int m = 0; m < 8; m++) {
        size_t row = (size_t)(M0 + m_sub + m);
        float pa[4], pi[4];
        unpack2(accA[m][0], pa[0], pa[1]);
        unpack2(accA[m][1], pa[2], pa[3]);
        unpack2(accI[m][0], pi[0], pi[1]);
        unpack2(accI[m][1], pi[2], pi[3]);
        float av[4], cv[4];
#pragma unroll
        for (int c = 0; c < 4; c++) {
            float pav = pa[c] + bav[c];
            float piv = pi[c] + biv[c];
            float rg = sigmoidf(pav);
            float ig = sigmoidf(piv);
            float al = sigmoidf(gav[c]);
            float aa = al * __expf(-LN3 * rg);
            float dr = sqrtf(fmaxf(1.0f - aa * aa, 0.0f)) * ig * piv;
            av[c] = aa;
            cv[c] = dr;
        }
        *(float4*)&g_A[row * Ii + icol] = make_float4(av[0], av[1], av[2], av[3]);
        *(float4*)&g_C[row * Ii + icol] = make_float4(cv[0], cv[1], cv[2], cv[3]);
    }
}

// ---------------------------------------------------------------------------
// Sequential scan over S. One thread per (b, i) chain; coalesced across i.
// Unroll 16 so the independent a/c loads of 16 future steps are batched in
// flight (latency-bound regime: only ~3.5 warps/SM).
// ---------------------------------------------------------------------------
__global__ __launch_bounds__(256)
void scan_kernel(float* __restrict__ out) {
    const int g = blockIdx.x * blockDim.x + threadIdx.x;   // 0..16383
    const int b = g >> 11;          // /2048
    const int i = g & 2047;
    size_t base = (size_t)b * Ss * Ii + i;

    float h = 0.0f;
#pragma unroll 16
    for (int s = 0; s < Ss; s++) {
        size_t idx = base + (size_t)s * Ii;
        float a = g_A[idx];
        float c = g_C[idx];
        h = fmaf(a, h, c);
        out[idx] = h;
    }
}

extern "C" void kernel_launch(void* const* d_in, const int* in_sizes, int n_in,
                              void* d_out, int out_size) {
    const float* x    = (const float*)d_in[0];
    const float* Wa   = (const float*)d_in[1];
    const float* ba   = (const float*)d_in[2];
    const float* Wi   = (const float*)d_in[3];
    const float* bi   = (const float*)d_in[4];
    const float* gate = (const float*)d_in[5];
    float* out = (float*)d_out;

    dim3 grid(Ii / 64, Mtot / 128);   // 32 x 128
    gemm_gate_kernel<<<grid, 256>>>(x, Wa, ba, Wi, bi, gate);
    scan_kernel<<<64, 256>>>(out);
}

// round 4
// speedup vs baseline: 2.4938x; 2.4938x over previous
#include <cuda_runtime.h>
#include <cuda_bf16.h>
#include <cstdint>

#define Bb 8
#define Ss 2048
#define Dd 512
#define Ii 2048
#define Mtot (Bb * Ss)           // 16384
#define LN3 1.0986122886681098f

// chunked scan config
#define NCH 16
#define CHS (Ss / NCH)           // 128
#define NCHAIN (Bb * Ii)         // 16384

// ---------------------------------------------------------------------------
// Device-global scratch
// ---------------------------------------------------------------------------
__device__ float g_A[(size_t)Mtot * Ii];
__device__ float g_C[(size_t)Mtot * Ii];
__device__ float g_P[NCH * NCHAIN];
__device__ float g_Q[NCH * NCHAIN];
__device__ float g_H0[NCH * NCHAIN];
__device__ __nv_bfloat16 g_xh[(size_t)Mtot * Dd];
__device__ __nv_bfloat16 g_xl[(size_t)Mtot * Dd];
__device__ __nv_bfloat16 g_wah[(size_t)Ii * Dd];
__device__ __nv_bfloat16 g_wal[(size_t)Ii * Dd];
__device__ __nv_bfloat16 g_wih[(size_t)Ii * Dd];
__device__ __nv_bfloat16 g_wil[(size_t)Ii * Dd];

// ---------------------------------------------------------------------------
// helpers
// ---------------------------------------------------------------------------
__device__ __forceinline__ uint32_t smem_u32(const void* p) {
    uint32_t a;
    asm("{ .reg .u64 t; cvta.to.shared.u64 t, %1; cvt.u32.u64 %0, t; }" : "=r"(a) : "l"(p));
    return a;
}
__device__ __forceinline__ float sigmoidf(float x) { return 1.0f / (1.0f + __expf(-x)); }

__device__ __forceinline__ void cp16(uint32_t dst, const void* src) {
    asm volatile("cp.async.cg.shared.global [%0], [%1], 16;" :: "r"(dst), "l"(src));
}
__device__ __forceinline__ void cp_commit() { asm volatile("cp.async.commit_group;"); }
__device__ __forceinline__ void cp_wait0()  { asm volatile("cp.async.wait_group 0;" ::: "memory"); }

__device__ __forceinline__ void ldsm4(uint32_t* r, uint32_t addr) {
    asm volatile("ldmatrix.sync.aligned.m8n8.x4.shared.b16 {%0,%1,%2,%3}, [%4];"
                 : "=r"(r[0]), "=r"(r[1]), "=r"(r[2]), "=r"(r[3]) : "r"(addr));
}
__device__ __forceinline__ void mma16816(float* c, const uint32_t* a, const uint32_t* b) {
    asm volatile(
        "mma.sync.aligned.m16n8k16.row.col.f32.bf16.bf16.f32 "
        "{%0,%1,%2,%3}, {%4,%5,%6,%7}, {%8,%9}, {%0,%1,%2,%3};"
        : "+f"(c[0]), "+f"(c[1]), "+f"(c[2]), "+f"(c[3])
        : "r"(a[0]), "r"(a[1]), "r"(a[2]), "r"(a[3]), "r"(b[0]), "r"(b[1]));
}

// ---------------------------------------------------------------------------
// Pre-pass: fp32 -> bf16 hi/lo split
// ---------------------------------------------------------------------------
__global__ __launch_bounds__(256)
void convert_split(const float* __restrict__ src,
                   __nv_bfloat16* __restrict__ hi,
                   __nv_bfloat16* __restrict__ lo, int n4) {
    int i = blockIdx.x * 256 + threadIdx.x;
    if (i >= n4) return;
    float4 v = ((const float4*)src)[i];
    float f[4] = {v.x, v.y, v.z, v.w};
    __nv_bfloat16 h[4], l[4];
#pragma unroll
    for (int j = 0; j < 4; j++) {
        h[j] = __float2bfloat16_rn(f[j]);
        l[j] = __float2bfloat16_rn(f[j] - __bfloat162float(h[j]));
    }
    ((uint2*)hi)[i] = *reinterpret_cast<uint2*>(h);
    ((uint2*)lo)[i] = *reinterpret_cast<uint2*>(l);
}

// ---------------------------------------------------------------------------
// GEMM: CTA tile 128(M) x 64(N), K-tile 32, 256 threads (8 warps: 4M x 2N,
// warp tile 32x32). Split-bf16 (hh + hl + lh) for both projections.
// Accumulators in registers; gate epilogue writes g_A/g_C.
// ---------------------------------------------------------------------------
#define BK 32
#define ROWB 80                 // 64B row + 16B pad -> ldmatrix conflict-free
#define SMA 10240               // 128 rows * 80B (per A array)
#define SMB 5120                // 64 rows * 80B (per W array)
#define SMBUF 40960             // 2*SMA + 4*SMB per buffer
#define SM_BIAS (2 * SMBUF)     // 81920
#define SMTOT (SM_BIAS + 3 * 64 * 4)

__global__ __launch_bounds__(256)
void gemm_gate(const float* __restrict__ ba,
               const float* __restrict__ bi,
               const float* __restrict__ gate) {
    extern __shared__ char smem[];
    const uint32_t sb = smem_u32(smem);
    const int tid = threadIdx.x;
    const int wid = tid >> 5;
    const int lane = tid & 31;
    const int wm = wid & 3;          // 0..3 (M)
    const int wn = wid >> 2;         // 0..1 (N)

    const int N0 = blockIdx.x * 64;
    const int M0 = blockIdx.y * 128;

    // stage biases / alpha
    float* bias_s = (float*)(smem + SM_BIAS);
    if (tid < 64) {
        bias_s[tid]       = ba[N0 + tid];
        bias_s[64 + tid]  = bi[N0 + tid];
        bias_s[128 + tid] = sigmoidf(gate[N0 + tid]);
    }

    // prefetch one K-tile into buffer `buf`
    auto prefetch = [&](int kt, int buf) {
        const int k0 = kt * BK;
        const uint32_t bufb = sb + buf * SMBUF;
#pragma unroll
        for (int i = 0; i < 8; i++) {
            int g = tid + i * 256;
            if (g < 1024) {
                int arr = g >> 9, r = (g >> 2) & 127, ch = g & 3;
                const __nv_bfloat16* src =
                    (arr ? g_xl : g_xh) + (size_t)(M0 + r) * Dd + k0 + ch * 8;
                cp16(bufb + arr * SMA + r * ROWB + ch * 16, src);
            } else {
                int h = g - 1024;
                int arr = h >> 8, r = (h >> 2) & 63, ch = h & 3;
                const __nv_bfloat16* wsrc;
                if      (arr == 0) wsrc = g_wah;
                else if (arr == 1) wsrc = g_wal;
                else if (arr == 2) wsrc = g_wih;
                else               wsrc = g_wil;
                cp16(bufb + 2 * SMA + arr * SMB + r * ROWB + ch * 16,
                     wsrc + (size_t)(N0 + r) * Dd + k0 + ch * 8);
            }
        }
        cp_commit();
    };

    float acc[2][2][4][4];           // [proj][mt][nt][c0..c3]
#pragma unroll
    for (int p = 0; p < 2; p++)
#pragma unroll
        for (int mt = 0; mt < 2; mt++)
#pragma unroll
            for (int nt = 0; nt < 4; nt++)
#pragma unroll
                for (int c = 0; c < 4; c++) acc[p][mt][nt][c] = 0.0f;

    prefetch(0, 0);

    const int NT = Dd / BK;          // 16
    for (int kt = 0; kt < NT; kt++) {
        const int buf = kt & 1;
        cp_wait0();
        __syncthreads();
        if (kt + 1 < NT) prefetch(kt + 1, buf ^ 1);

        const uint32_t bufb = sb + buf * SMBUF;
#pragma unroll
        for (int ks = 0; ks < 2; ks++) {
            // A fragments (hi & lo) for 2 m-tiles
            uint32_t ah[2][4], al[2][4];
#pragma unroll
            for (int mt = 0; mt < 2; mt++) {
                uint32_t roff = (uint32_t)((wm * 32 + mt * 16 + (lane & 15)) * ROWB +
                                           ((lane >> 4) + 2 * ks) * 16);
                ldsm4(ah[mt], bufb + roff);
                ldsm4(al[mt], bufb + SMA + roff);
            }
            // per projection: B fragments + 3-pass MMA
#pragma unroll
            for (int p = 0; p < 2; p++) {
                uint32_t bh[8], bl[8];
                uint32_t nbase = (uint32_t)((wn * 32 + (lane & 7) + ((lane >> 4) << 3)) * ROWB +
                                            (((lane >> 3) & 1) + 2 * ks) * 16);
#pragma unroll
                for (int np = 0; np < 2; np++) {
                    uint32_t roff = nbase + (uint32_t)(np * 16 * ROWB);
                    ldsm4(&bh[np * 4], bufb + 2 * SMA + (2 * p) * SMB + roff);
                    ldsm4(&bl[np * 4], bufb + 2 * SMA + (2 * p + 1) * SMB + roff);
                }
#pragma unroll
                for (int mt = 0; mt < 2; mt++)
#pragma unroll
                    for (int nt = 0; nt < 4; nt++) {
                        const uint32_t* b0h = &bh[(nt >> 1) * 4 + (nt & 1) * 2];
                        const uint32_t* b0l = &bl[(nt >> 1) * 4 + (nt & 1) * 2];
                        mma16816(acc[p][mt][nt], ah[mt], b0h);
                        mma16816(acc[p][mt][nt], ah[mt], b0l);
                        mma16816(acc[p][mt][nt], al[mt], b0h);
                    }
            }
        }
        __syncthreads();
    }

    // ---- gate epilogue ----
#pragma unroll
    for (int mt = 0; mt < 2; mt++)
#pragma unroll
        for (int nt = 0; nt < 4; nt++)
#pragma unroll
            for (int half = 0; half < 2; half++) {
                int row = M0 + wm * 32 + mt * 16 + (lane >> 2) + half * 8;
                int coll = wn * 32 + nt * 8 + (lane & 3) * 2;   // 0..63 local
                float pa0 = acc[0][mt][nt][half * 2 + 0] + bias_s[coll];
                float pa1 = acc[0][mt][nt][half * 2 + 1] + bias_s[coll + 1];
                float pi0 = acc[1][mt][nt][half * 2 + 0] + bias_s[64 + coll];
                float pi1 = acc[1][mt][nt][half * 2 + 1] + bias_s[64 + coll + 1];
                float al0 = bias_s[128 + coll], al1 = bias_s[128 + coll + 1];

                float aa0 = al0 * __expf(-LN3 * sigmoidf(pa0));
                float aa1 = al1 * __expf(-LN3 * sigmoidf(pa1));
                float cv0 = sqrtf(fmaxf(1.0f - aa0 * aa0, 0.0f)) * sigmoidf(pi0) * pi0;
                float cv1 = sqrtf(fmaxf(1.0f - aa1 * aa1, 0.0f)) * sigmoidf(pi1) * pi1;

                size_t o = (size_t)row * Ii + N0 + coll;
                *(float2*)&g_A[o] = make_float2(aa0, aa1);
                *(float2*)&g_C[o] = make_float2(cv0, cv1);
            }
}

// ---------------------------------------------------------------------------
// Chunked scan
// ---------------------------------------------------------------------------
__global__ __launch_bounds__(256)
void scanA() {
    int t = blockIdx.x * 256 + threadIdx.x;
    int i = t & 2047;
    int rest = t >> 11;
    int b = rest & 7;
    int q = rest >> 3;
    size_t base = ((size_t)(b * Ss + q * CHS)) * Ii + i;
    float h = 0.0f, P = 1.0f;
#pragma unroll 16
    for (int s = 0; s < CHS; s++) {
        float a = g_A[base + (size_t)s * Ii];
        float c = g_C[base + (size_t)s * Ii];
        h = fmaf(a, h, c);
        P *= a;
    }
    int chain = b * Ii + i;
    g_P[q * NCHAIN + chain] = P;
    g_Q[q * NCHAIN + chain] = h;
}

__global__ __launch_bounds__(256)
void scanB() {
    int t = blockIdx.x * 256 + threadIdx.x;
    float carry = 0.0f;
#pragma unroll
    for (int q = 0; q < NCH; q++) {
        g_H0[q * NCHAIN + t] = carry;
        carry = fmaf(g_P[q * NCHAIN + t], carry, g_Q[q * NCHAIN + t]);
    }
}

__global__ __launch_bounds__(256)
void scanC(float* __restrict__ out) {
    int t = blockIdx.x * 256 + threadIdx.x;
    int i = t & 2047;
    int rest = t >> 11;
    int b = rest & 7;
    int q = rest >> 3;
    size_t base = ((size_t)(b * Ss + q * CHS)) * Ii + i;
    float h = g_H0[q * NCHAIN + b * Ii + i];
#pragma unroll 16
    for (int s = 0; s < CHS; s++) {
        size_t idx = base + (size_t)s * Ii;
        h = fmaf(g_A[idx], h, g_C[idx]);
        out[idx] = h;
    }
}

extern "C" void kernel_launch(void* const* d_in, const int* in_sizes, int n_in,
                              void* d_out, int out_size) {
    const float* x    = (const float*)d_in[0];
    const float* Wa   = (const float*)d_in[1];
    const float* ba   = (const float*)d_in[2];
    const float* Wi   = (const float*)d_in[3];
    const float* bi   = (const float*)d_in[4];
    const float* gate = (const float*)d_in[5];
    float* out = (float*)d_out;

    // resolve device-global scratch addresses for the convert kernels
    __nv_bfloat16 *xh, *xl, *wah, *wal, *wih, *wil;
    cudaGetSymbolAddress((void**)&xh,  g_xh);
    cudaGetSymbolAddress((void**)&xl,  g_xl);
    cudaGetSymbolAddress((void**)&wah, g_wah);
    cudaGetSymbolAddress((void**)&wal, g_wal);
    cudaGetSymbolAddress((void**)&wih, g_wih);
    cudaGetSymbolAddress((void**)&wil, g_wil);

    convert_split<<<(Mtot * Dd / 4 + 255) / 256, 256>>>(x, xh, xl, Mtot * Dd / 4);
    convert_split<<<(Ii * Dd / 4 + 255) / 256, 256>>>(Wa, wah, wal, Ii * Dd / 4);
    convert_split<<<(Ii * Dd / 4 + 255) / 256, 256>>>(Wi, wih, wil, Ii * Dd / 4);

    cudaFuncSetAttribute(gemm_gate, cudaFuncAttributeMaxDynamicSharedMemorySize, SMTOT);
    dim3 grid(Ii / 64, Mtot / 128);          // (32, 128), N fastest
    gemm_gate<<<grid, 256, SMTOT>>>(ba, bi, gate);

    scanA<<<(NCH * NCHAIN) / 256, 256>>>();
    scanB<<<NCHAIN / 256, 256>>>();
    scanC<<<(NCH * NCHAIN) / 256, 256>>>(out);
}

// round 7
// speedup vs baseline: 2.6917x; 1.0794x over previous
#include <cuda_runtime.h>
#include <cuda_bf16.h>
#include <cstdint>

#define Bb 8
#define Ss 2048
#define Dd 512
#define Ii 2048
#define Mtot (Bb * Ss)           // 16384
#define LN3 1.0986122886681098f

// chunked scan config
#define NCH 16
#define CHS (Ss / NCH)           // 128
#define NCHAIN (Bb * Ii)         // 16384

// ---------------------------------------------------------------------------
// Device-global scratch
// ---------------------------------------------------------------------------
__device__ float g_A[(size_t)Mtot * Ii];
__device__ float g_C[(size_t)Mtot * Ii];
__device__ float g_P[NCH * NCHAIN];
__device__ float g_Q[NCH * NCHAIN];
__device__ float g_H0[NCH * NCHAIN];

// ---------------------------------------------------------------------------
// helpers
// ---------------------------------------------------------------------------
__device__ __forceinline__ uint32_t smem_u32(const void* p) {
    uint32_t a;
    asm("{ .reg .u64 t; cvta.to.shared.u64 t, %1; cvt.u32.u64 %0, t; }" : "=r"(a) : "l"(p));
    return a;
}
__device__ __forceinline__ float sigmoidf(float x) { return 1.0f / (1.0f + __expf(-x)); }

__device__ __forceinline__ void cp16(uint32_t dst, const void* src) {
    asm volatile("cp.async.cg.shared.global [%0], [%1], 16;" :: "r"(dst), "l"(src));
}
__device__ __forceinline__ void cp_commit() { asm volatile("cp.async.commit_group;"); }
__device__ __forceinline__ void cp_wait0()  { asm volatile("cp.async.wait_group 0;" ::: "memory"); }

__device__ __forceinline__ uint32_t to_tf32(float f) {
    uint32_t r;
    asm("cvt.rna.tf32.f32 %0, %1;" : "=r"(r) : "f"(f));
    return r;
}
__device__ __forceinline__ void mma_tf32(float* c, const uint32_t* a, const uint32_t* b) {
    asm volatile(
        "mma.sync.aligned.m16n8k8.row.col.f32.tf32.tf32.f32 "
        "{%0,%1,%2,%3}, {%4,%5,%6,%7}, {%8,%9}, {%0,%1,%2,%3};"
        : "+f"(c[0]), "+f"(c[1]), "+f"(c[2]), "+f"(c[3])
        : "r"(a[0]), "r"(a[1]), "r"(a[2]), "r"(a[3]), "r"(b[0]), "r"(b[1]));
}

// ---------------------------------------------------------------------------
// GEMM: CTA tile 128(M) x 64(N), K-tile 32 (4 k8 steps), 256 threads
// (8 warps: 4M x 2N, warp tile 32x32). Single-pass tf32 mma for both
// projections. fp32 tiles in smem with +4-float row pad (stride 36 floats,
// 36 % 32 == 4 -> all fragment access patterns bank-conflict-free).
// ---------------------------------------------------------------------------
#define BK 32
#define ROWF 36                  // floats per row (32 + 4 pad)
#define ROWB (ROWF * 4)          // 144 bytes
#define SMA (128 * ROWB)         // 18432 B
#define SMW (64 * ROWB)          // 9216 B
#define SMBUF (SMA + 2 * SMW)    // 36864 B
#define SM_BIAS (2 * SMBUF)      // 73728
#define SMTOT (SM_BIAS + 3 * 64 * 4)

__global__ __launch_bounds__(256)
void gemm_gate(const float* __restrict__ x,
               const float* __restrict__ Wa,
               const float* __restrict__ Wi,
               const float* __restrict__ ba,
               const float* __restrict__ bi,
               const float* __restrict__ gate) {
    extern __shared__ char smem[];
    const uint32_t sb = smem_u32(smem);
    const int tid = threadIdx.x;
    const int wid = tid >> 5;
    const int lane = tid & 31;
    const int gid = lane >> 2;       // 0..7
    const int tig = lane & 3;        // 0..3
    const int wm = wid & 3;          // 0..3 (M)
    const int wn = wid >> 2;         // 0..1 (N)

    const int N0 = blockIdx.x * 64;
    const int M0 = blockIdx.y * 128;

    // stage biases / alpha
    float* bias_s = (float*)(smem + SM_BIAS);
    if (tid < 64) {
        bias_s[tid]       = ba[N0 + tid];
        bias_s[64 + tid]  = bi[N0 + tid];
        bias_s[128 + tid] = sigmoidf(gate[N0 + tid]);
    }

    // prefetch one K-tile into buffer `buf` (2048 cp16, 8 per thread)
    auto prefetch = [&](int kt, int buf) {
        const int k0 = kt * BK;
        const uint32_t bufb = sb + buf * SMBUF;
#pragma unroll
        for (int i = 0; i < 8; i++) {
            int g = tid + i * 256;
            if (g < 1024) {
                int r = g >> 3, ch = g & 7;
                cp16(bufb + r * ROWB + ch * 16,
                     x + (size_t)(M0 + r) * Dd + k0 + ch * 4);
            } else {
                int h = g - 1024;
                int p = h >> 9, r = (h >> 3) & 63, ch = h & 7;
                const float* wsrc = p ? Wi : Wa;
                cp16(bufb + SMA + p * SMW + r * ROWB + ch * 16,
                     wsrc + (size_t)(N0 + r) * Dd + k0 + ch * 4);
            }
        }
        cp_commit();
    };

    float acc[2][2][4][4];           // [proj][mt][nt][c]
#pragma unroll
    for (int p = 0; p < 2; p++)
#pragma unroll
        for (int mt = 0; mt < 2; mt++)
#pragma unroll
            for (int nt = 0; nt < 4; nt++)
#pragma unroll
                for (int c = 0; c < 4; c++) acc[p][mt][nt][c] = 0.0f;

    prefetch(0, 0);

    const int NT = Dd / BK;          // 16
    for (int kt = 0; kt < NT; kt++) {
        const int buf = kt & 1;
        cp_wait0();
        __syncthreads();
        if (kt + 1 < NT) prefetch(kt + 1, buf ^ 1);

        const float* As = (const float*)(smem + buf * SMBUF);
        const float* Ws0 = (const float*)(smem + buf * SMBUF + SMA);
        const float* Ws1 = (const float*)(smem + buf * SMBUF + SMA + SMW);

#pragma unroll
        for (int s = 0; s < 4; s++) {           // 4 k8 steps
            const int kb = s * 8;
            // A fragments for 2 m-tiles
            uint32_t af[2][4];
#pragma unroll
            for (int mt = 0; mt < 2; mt++) {
                int rbase = (wm * 32 + mt * 16 + gid) * ROWF + kb + tig;
                af[mt][0] = to_tf32(As[rbase]);
                af[mt][1] = to_tf32(As[rbase + 8 * ROWF]);
                af[mt][2] = to_tf32(As[rbase + 4]);
                af[mt][3] = to_tf32(As[rbase + 8 * ROWF + 4]);
            }
#pragma unroll
            for (int p = 0; p < 2; p++) {
                const float* Ws = p ? Ws1 : Ws0;
                uint32_t bf[4][2];
#pragma unroll
                for (int nt = 0; nt < 4; nt++) {
                    int nbase = (wn * 32 + nt * 8 + gid) * ROWF + kb + tig;
                    bf[nt][0] = to_tf32(Ws[nbase]);
                    bf[nt][1] = to_tf32(Ws[nbase + 4]);
                }
#pragma unroll
                for (int mt = 0; mt < 2; mt++)
#pragma unroll
                    for (int nt = 0; nt < 4; nt++)
                        mma_tf32(acc[p][mt][nt], af[mt], bf[nt]);
            }
        }
        __syncthreads();
    }

    // ---- gate epilogue ----
#pragma unroll
    for (int mt = 0; mt < 2; mt++)
#pragma unroll
        for (int nt = 0; nt < 4; nt++)
#pragma unroll
            for (int half = 0; half < 2; half++) {
                int row = M0 + wm * 32 + mt * 16 + gid + half * 8;
                int coll = wn * 32 + nt * 8 + tig * 2;   // 0..63 local
                float pa0 = acc[0][mt][nt][half * 2 + 0] + bias_s[coll];
                float pa1 = acc[0][mt][nt][half * 2 + 1] + bias_s[coll + 1];
                float pi0 = acc[1][mt][nt][half * 2 + 0] + bias_s[64 + coll];
                float pi1 = acc[1][mt][nt][half * 2 + 1] + bias_s[64 + coll + 1];
                float al0 = bias_s[128 + coll], al1 = bias_s[128 + coll + 1];

                float aa0 = al0 * __expf(-LN3 * sigmoidf(pa0));
                float aa1 = al1 * __expf(-LN3 * sigmoidf(pa1));
                float cv0 = sqrtf(fmaxf(1.0f - aa0 * aa0, 0.0f)) * sigmoidf(pi0) * pi0;
                float cv1 = sqrtf(fmaxf(1.0f - aa1 * aa1, 0.0f)) * sigmoidf(pi1) * pi1;

                size_t o = (size_t)row * Ii + N0 + coll;
                *(float2*)&g_A[o] = make_float2(aa0, aa1);
                *(float2*)&g_C[o] = make_float2(cv0, cv1);
            }
}

// ---------------------------------------------------------------------------
// Chunked scan
// ---------------------------------------------------------------------------
__global__ __launch_bounds__(256)
void scanA() {
    int t = blockIdx.x * 256 + threadIdx.x;
    int i = t & 2047;
    int rest = t >> 11;
    int b = rest & 7;
    int q = rest >> 3;
    size_t base = ((size_t)(b * Ss + q * CHS)) * Ii + i;
    float h = 0.0f, P = 1.0f;
#pragma unroll 16
    for (int s = 0; s < CHS; s++) {
        float a = g_A[base + (size_t)s * Ii];
        float c = g_C[base + (size_t)s * Ii];
        h = fmaf(a, h, c);
        P *= a;
    }
    int chain = b * Ii + i;
    g_P[q * NCHAIN + chain] = P;
    g_Q[q * NCHAIN + chain] = h;
}

__global__ __launch_bounds__(256)
void scanB() {
    int t = blockIdx.x * 256 + threadIdx.x;
    float carry = 0.0f;
#pragma unroll
    for (int q = 0; q < NCH; q++) {
        g_H0[q * NCHAIN + t] = carry;
        carry = fmaf(g_P[q * NCHAIN + t], carry, g_Q[q * NCHAIN + t]);
    }
}

__global__ __launch_bounds__(256)
void scanC(float* __restrict__ out) {
    int t = blockIdx.x * 256 + threadIdx.x;
    int i = t & 2047;
    int rest = t >> 11;
    int b = rest & 7;
    int q = rest >> 3;
    size_t base = ((size_t)(b * Ss + q * CHS)) * Ii + i;
    float h = g_H0[q * NCHAIN + b * Ii + i];
#pragma unroll 16
    for (int s = 0; s < CHS; s++) {
        size_t idx = base + (size_t)s * Ii;
        h = fmaf(g_A[idx], h, g_C[idx]);
        out[idx] = h;
    }
}

extern "C" void kernel_launch(void* const* d_in, const int* in_sizes, int n_in,
                              void* d_out, int out_size) {
    const float* x    = (const float*)d_in[0];
    const float* Wa   = (const float*)d_in[1];
    const float* ba   = (const float*)d_in[2];
    const float* Wi   = (const float*)d_in[3];
    const float* bi   = (const float*)d_in[4];
    const float* gate = (const float*)d_in[5];
    float* out = (float*)d_out;

    cudaFuncSetAttribute(gemm_gate, cudaFuncAttributeMaxDynamicSharedMemorySize, SMTOT);
    dim3 grid(Ii / 64, Mtot / 128);          // (32, 128), N fastest
    gemm_gate<<<grid, 256, SMTOT>>>(x, Wa, Wi, ba, bi, gate);

    scanA<<<(NCH * NCHAIN) / 256, 256>>>();
    scanB<<<NCHAIN / 256, 256>>>();
    scanC<<<(NCH * NCHAIN) / 256, 256>>>(out);
}

// round 8
// speedup vs baseline: 2.9484x; 1.0953x over previous
#include <cuda_runtime.h>
#include <cuda_bf16.h>
#include <cstdint>

#define Bb 8
#define Ss 2048
#define Dd 512
#define Ii 2048
#define Mtot (Bb * Ss)           // 16384
#define LN3 1.0986122886681098f

// chunked scan config
#define NCH 16
#define CHS (Ss / NCH)           // 128  (== GEMM M-tile: scanA fuses into GEMM)
#define NCHAIN (Bb * Ii)         // 16384

// ---------------------------------------------------------------------------
// Device-global scratch
// ---------------------------------------------------------------------------
__device__ float g_A[(size_t)Mtot * Ii];
__device__ float g_C[(size_t)Mtot * Ii];
__device__ float g_P[NCH * NCHAIN];
__device__ float g_Q[NCH * NCHAIN];
__device__ float g_H0[NCH * NCHAIN];

// ---------------------------------------------------------------------------
// helpers
// ---------------------------------------------------------------------------
__device__ __forceinline__ uint32_t smem_u32(const void* p) {
    uint32_t a;
    asm("{ .reg .u64 t; cvta.to.shared.u64 t, %1; cvt.u32.u64 %0, t; }" : "=r"(a) : "l"(p));
    return a;
}
__device__ __forceinline__ float sigmoidf(float x) { return 1.0f / (1.0f + __expf(-x)); }

__device__ __forceinline__ void cp16(uint32_t dst, const void* src) {
    asm volatile("cp.async.cg.shared.global [%0], [%1], 16;" :: "r"(dst), "l"(src));
}
__device__ __forceinline__ void cp_commit() { asm volatile("cp.async.commit_group;"); }
__device__ __forceinline__ void cp_wait0()  { asm volatile("cp.async.wait_group 0;" ::: "memory"); }

__device__ __forceinline__ uint32_t to_tf32(float f) {
    uint32_t r;
    asm("cvt.rna.tf32.f32 %0, %1;" : "=r"(r) : "f"(f));
    return r;
}
__device__ __forceinline__ void ldsm4(uint32_t* r, uint32_t addr) {
    asm volatile("ldmatrix.sync.aligned.m8n8.x4.shared.b16 {%0,%1,%2,%3}, [%4];"
                 : "=r"(r[0]), "=r"(r[1]), "=r"(r[2]), "=r"(r[3]) : "r"(addr));
}
__device__ __forceinline__ void mma_tf32(float* c, const uint32_t* a, const uint32_t* b) {
    asm volatile(
        "mma.sync.aligned.m16n8k8.row.col.f32.tf32.tf32.f32 "
        "{%0,%1,%2,%3}, {%4,%5,%6,%7}, {%8,%9}, {%0,%1,%2,%3};"
        : "+f"(c[0]), "+f"(c[1]), "+f"(c[2]), "+f"(c[3])
        : "r"(a[0]), "r"(a[1]), "r"(a[2]), "r"(a[3]), "r"(b[0]), "r"(b[1]));
}

// ---------------------------------------------------------------------------
// GEMM: CTA tile 128(M) x 64(N), K-tile 32, 256 threads (8 warps: 4M x 2N,
// warp tile 32x32). tf32 mma, fragments via ldmatrix-on-fp32 (b16 x4 trick).
// Epilogue: gate math -> g_A/g_C, PLUS fused per-chunk scan summary (P,Q).
// ---------------------------------------------------------------------------
#define BK 32
#define ROWF 36                  // floats per row (32 + 4 pad); 144B rows
#define ROWB (ROWF * 4)
#define SMA (128 * ROWB)         // 18432 B
#define SMW (64 * ROWB)          // 9216 B
#define SMBUF (SMA + 2 * SMW)    // 36864 B
#define SM_BIAS (2 * SMBUF)      // 73728
#define SMTOT (SM_BIAS + 3 * 64 * 4)
// epilogue scan tiles (alias the double buffers after the mainloop)
#define EROW 68                  // 64 + 4 pad floats
#define SM_SC (128 * EROW * 4)   // sC offset = 34816

__global__ __launch_bounds__(256)
void gemm_gate(const float* __restrict__ x,
               const float* __restrict__ Wa,
               const float* __restrict__ Wi,
               const float* __restrict__ ba,
               const float* __restrict__ bi,
               const float* __restrict__ gate) {
    extern __shared__ char smem[];
    const uint32_t sb = smem_u32(smem);
    const int tid = threadIdx.x;
    const int wid = tid >> 5;
    const int lane = tid & 31;
    const int gid = lane >> 2;       // 0..7
    const int tig = lane & 3;        // 0..3
    const int wm = wid & 3;          // M warp 0..3
    const int wn = wid >> 2;         // N warp 0..1

    const int N0 = blockIdx.x * 64;
    const int M0 = blockIdx.y * 128;

    float* bias_s = (float*)(smem + SM_BIAS);
    if (tid < 64) {
        bias_s[tid]       = ba[N0 + tid];
        bias_s[64 + tid]  = bi[N0 + tid];
        bias_s[128 + tid] = sigmoidf(gate[N0 + tid]);
    }

    auto prefetch = [&](int kt, int buf) {
        const int k0 = kt * BK;
        const uint32_t bufb = sb + buf * SMBUF;
#pragma unroll
        for (int i = 0; i < 8; i++) {
            int g = tid + i * 256;
            if (g < 1024) {
                int r = g >> 3, ch = g & 7;
                cp16(bufb + r * ROWB + ch * 16,
                     x + (size_t)(M0 + r) * Dd + k0 + ch * 4);
            } else {
                int h = g - 1024;
                int p = h >> 9, r = (h >> 3) & 63, ch = h & 7;
                const float* wsrc = p ? Wi : Wa;
                cp16(bufb + SMA + p * SMW + r * ROWB + ch * 16,
                     wsrc + (size_t)(N0 + r) * Dd + k0 + ch * 4);
            }
        }
        cp_commit();
    };

    // ldmatrix lane->row address offsets (in bytes, within a buffer)
    const int mtx = lane >> 3;       // matrix index 0..3
    const int mrow = lane & 7;
    // A: matrices [m0-7,k0-3][m8-15,k0-3][m0-7,k4-7][m8-15,k4-7]
    const uint32_t aoff = (uint32_t)(((wm * 32 + (mtx & 1) * 8 + mrow) * ROWF +
                                      (mtx >> 1) * 4) * 4);
    // B: matrices [n0-7,k0-3][n0-7,k4-7][n8-15,k0-3][n8-15,k4-7]
    const uint32_t boff = (uint32_t)(((wn * 32 + (mtx >> 1) * 8 + mrow) * ROWF +
                                      (mtx & 1) * 4) * 4);

    float acc[2][2][4][4];           // [proj][mt][nt][c]
#pragma unroll
    for (int p = 0; p < 2; p++)
#pragma unroll
        for (int mt = 0; mt < 2; mt++)
#pragma unroll
            for (int nt = 0; nt < 4; nt++)
#pragma unroll
                for (int c = 0; c < 4; c++) acc[p][mt][nt][c] = 0.0f;

    prefetch(0, 0);

    const int NT = Dd / BK;          // 16
    for (int kt = 0; kt < NT; kt++) {
        const int buf = kt & 1;
        cp_wait0();
        __syncthreads();             // also orders buffer reuse (no tail sync)
        if (kt + 1 < NT) prefetch(kt + 1, buf ^ 1);

        const uint32_t Ab = sb + buf * SMBUF;
        const uint32_t Wb = Ab + SMA;

#pragma unroll
        for (int s = 0; s < 4; s++) {
            const uint32_t ks = (uint32_t)(s * 32);       // 8 floats
            uint32_t araw[2][4], af[2][4];
#pragma unroll
            for (int mt = 0; mt < 2; mt++) {
                ldsm4(araw[mt], Ab + aoff + ks + (uint32_t)(mt * 16 * ROWB));
#pragma unroll
                for (int c = 0; c < 4; c++) af[mt][c] = to_tf32(__uint_as_float(araw[mt][c]));
            }
#pragma unroll
            for (int p = 0; p < 2; p++) {
                const uint32_t Wp = Wb + (uint32_t)(p * SMW);
                uint32_t braw[2][4], bf[4][2];
#pragma unroll
                for (int ntp = 0; ntp < 2; ntp++) {
                    ldsm4(braw[ntp], Wp + boff + ks + (uint32_t)(ntp * 16 * ROWB));
                    bf[ntp * 2 + 0][0] = to_tf32(__uint_as_float(braw[ntp][0]));
                    bf[ntp * 2 + 0][1] = to_tf32(__uint_as_float(braw[ntp][1]));
                    bf[ntp * 2 + 1][0] = to_tf32(__uint_as_float(braw[ntp][2]));
                    bf[ntp * 2 + 1][1] = to_tf32(__uint_as_float(braw[ntp][3]));
                }
#pragma unroll
                for (int mt = 0; mt < 2; mt++)
#pragma unroll
                    for (int nt = 0; nt < 4; nt++)
                        mma_tf32(acc[p][mt][nt], af[mt], bf[nt]);
            }
        }
    }
    __syncthreads();                 // mainloop done; smem buffers now reusable

    // ---- gate epilogue: write g_A/g_C and stash tiles in smem ----
    float* sA = (float*)smem;                 // [128][EROW]
    float* sC = (float*)(smem + SM_SC);
#pragma unroll
    for (int mt = 0; mt < 2; mt++)
#pragma unroll
        for (int nt = 0; nt < 4; nt++)
#pragma unroll
            for (int half = 0; half < 2; half++) {
                int rl = wm * 32 + mt * 16 + gid + half * 8;     // local row
                int cl = wn * 32 + nt * 8 + tig * 2;             // local col
                float pa0 = acc[0][mt][nt][half * 2 + 0] + bias_s[cl];
                float pa1 = acc[0][mt][nt][half * 2 + 1] + bias_s[cl + 1];
                float pi0 = acc[1][mt][nt][half * 2 + 0] + bias_s[64 + cl];
                float pi1 = acc[1][mt][nt][half * 2 + 1] + bias_s[64 + cl + 1];
                float al0 = bias_s[128 + cl], al1 = bias_s[128 + cl + 1];

                float aa0 = al0 * __expf(-LN3 * sigmoidf(pa0));
                float aa1 = al1 * __expf(-LN3 * sigmoidf(pa1));
                float cv0 = sqrtf(fmaxf(1.0f - aa0 * aa0, 0.0f)) * sigmoidf(pi0) * pi0;
                float cv1 = sqrtf(fmaxf(1.0f - aa1 * aa1, 0.0f)) * sigmoidf(pi1) * pi1;

                size_t o = (size_t)(M0 + rl) * Ii + N0 + cl;
                *(float2*)&g_A[o] = make_float2(aa0, aa1);
                *(float2*)&g_C[o] = make_float2(cv0, cv1);
                sA[rl * EROW + cl] = aa0;  sA[rl * EROW + cl + 1] = aa1;
                sC[rl * EROW + cl] = cv0;  sC[rl * EROW + cl + 1] = cv1;
            }
    __syncthreads();

    // ---- fused scanA: this M-tile is exactly chunk (b, q) of 128 steps ----
    if (tid < 64) {
        const int col = tid;
        float h = 0.0f, P = 1.0f;
#pragma unroll 8
        for (int r = 0; r < 128; r++) {
            float a = sA[r * EROW + col];
            float c = sC[r * EROW + col];
            h = fmaf(a, h, c);
            P *= a;
        }
        const int b = M0 >> 11;                  // M0 / Ss
        const int q = (M0 & 2047) >> 7;          // chunk within sequence
        const int chain = b * Ii + N0 + col;
        g_P[q * NCHAIN + chain] = P;
        g_Q[q * NCHAIN + chain] = h;
    }
}

// ---------------------------------------------------------------------------
// scanB: compose chunk summaries per chain (serial over 16 chunks)
// ---------------------------------------------------------------------------
__global__ __launch_bounds__(256)
void scanB() {
    int t = blockIdx.x * 256 + threadIdx.x;
    float carry = 0.0f;
#pragma unroll
    for (int q = 0; q < NCH; q++) {
        g_H0[q * NCHAIN + t] = carry;
        carry = fmaf(g_P[q * NCHAIN + t], carry, g_Q[q * NCHAIN + t]);
    }
}

// ---------------------------------------------------------------------------
// scanC: replay with correct carry-in
// ---------------------------------------------------------------------------
__global__ __launch_bounds__(256)
void scanC(float* __restrict__ out) {
    int t = blockIdx.x * 256 + threadIdx.x;
    int i = t & 2047;
    int rest = t >> 11;
    int b = rest & 7;
    int q = rest >> 3;
    size_t base = ((size_t)(b * Ss + q * CHS)) * Ii + i;
    float h = g_H0[q * NCHAIN + b * Ii + i];
#pragma unroll 16
    for (int s = 0; s < CHS; s++) {
        size_t idx = base + (size_t)s * Ii;
        h = fmaf(g_A[idx], h, g_C[idx]);
        out[idx] = h;
    }
}

extern "C" void kernel_launch(void* const* d_in, const int* in_sizes, int n_in,
                              void* d_out, int out_size) {
    const float* x    = (const float*)d_in[0];
    const float* Wa   = (const float*)d_in[1];
    const float* ba   = (const float*)d_in[2];
    const float* Wi   = (const float*)d_in[3];
    const float* bi   = (const float*)d_in[4];
    const float* gate = (const float*)d_in[5];
    float* out = (float*)d_out;

    cudaFuncSetAttribute(gemm_gate, cudaFuncAttributeMaxDynamicSharedMemorySize, SMTOT);
    dim3 grid(Ii / 64, Mtot / 128);          // (32, 128), N fastest
    gemm_gate<<<grid, 256, SMTOT>>>(x, Wa, Wi, ba, bi, gate);

    scanB<<<NCHAIN / 256, 256>>>();
    scanC<<<(NCH * NCHAIN) / 256, 256>>>(out);
}

// round 11
// speedup vs baseline: 3.1987x; 1.0849x over previous
#include <cuda_runtime.h>
#include <cuda_bf16.h>
#include <cstdint>

#define Bb 8
#define Ss 2048
#define Dd 512
#define Ii 2048
#define Mtot (Bb * Ss)           // 16384
#define LN3 1.0986122886681098f

// chunked scan config
#define NCH 16
#define CHS (Ss / NCH)           // 128  (== GEMM M-tile: scanA fused into GEMM)
#define NCHAIN (Bb * Ii)         // 16384

// ---------------------------------------------------------------------------
// Device-global scratch
// ---------------------------------------------------------------------------
__device__ float g_A[(size_t)Mtot * Ii];
__device__ float g_C[(size_t)Mtot * Ii];
__device__ float g_P[NCH * NCHAIN];
__device__ float g_Q[NCH * NCHAIN];
__device__ float g_H0[NCH * NCHAIN];
// tf32-rounded copies (low 13 mantissa bits zero)
__device__ float g_xr[(size_t)Mtot * Dd];
__device__ float g_war[(size_t)Ii * Dd];
__device__ float g_wir[(size_t)Ii * Dd];

// ---------------------------------------------------------------------------
// helpers
// ---------------------------------------------------------------------------
__device__ __forceinline__ uint32_t smem_u32(const void* p) {
    uint32_t a;
    asm("{ .reg .u64 t; cvta.to.shared.u64 t, %1; cvt.u32.u64 %0, t; }" : "=r"(a) : "l"(p));
    return a;
}
__device__ __forceinline__ float sigmoidf(float x) { return 1.0f / (1.0f + __expf(-x)); }

__device__ __forceinline__ void cp16(uint32_t dst, const void* src) {
    asm volatile("cp.async.cg.shared.global [%0], [%1], 16;" :: "r"(dst), "l"(src));
}
__device__ __forceinline__ void cp_commit() { asm volatile("cp.async.commit_group;"); }
__device__ __forceinline__ void cp_wait0()  { asm volatile("cp.async.wait_group 0;" ::: "memory"); }

__device__ __forceinline__ uint32_t to_tf32(float f) {
    uint32_t r;
    asm("cvt.rna.tf32.f32 %0, %1;" : "=r"(r) : "f"(f));
    return r;
}
__device__ __forceinline__ void ldsm4(uint32_t* r, uint32_t addr) {
    asm volatile("ldmatrix.sync.aligned.m8n8.x4.shared.b16 {%0,%1,%2,%3}, [%4];"
                 : "=r"(r[0]), "=r"(r[1]), "=r"(r[2]), "=r"(r[3]) : "r"(addr));
}
__device__ __forceinline__ void mma_tf32(float* c, const uint32_t* a, const uint32_t* b) {
    asm volatile(
        "mma.sync.aligned.m16n8k8.row.col.f32.tf32.tf32.f32 "
        "{%0,%1,%2,%3}, {%4,%5,%6,%7}, {%8,%9}, {%0,%1,%2,%3};"
        : "+f"(c[0]), "+f"(c[1]), "+f"(c[2]), "+f"(c[3])
        : "r"(a[0]), "r"(a[1]), "r"(a[2]), "r"(a[3]), "r"(b[0]), "r"(b[1]));
}

// ---------------------------------------------------------------------------
// Pre-pass: round fp32 -> tf32 precision (stored as fp32). Mainloop then
// feeds raw bits to the MMA with no per-fragment CVT.
// ---------------------------------------------------------------------------
__global__ __launch_bounds__(256)
void round_tf32(const float* __restrict__ src, float* __restrict__ dst, int n4) {
    int i = blockIdx.x * 256 + threadIdx.x;
    if (i >= n4) return;
    float4 v = ((const float4*)src)[i];
    uint4 o;
    o.x = to_tf32(v.x); o.y = to_tf32(v.y);
    o.z = to_tf32(v.z); o.w = to_tf32(v.w);
    ((uint4*)dst)[i] = o;
}

// ---------------------------------------------------------------------------
// GEMM: CTA tile 128(M) x 64(N), K-tile 32, 256 threads (8 warps: 4M x 2N,
// warp tile 32x32). tf32 mma; fragments via ldmatrix-on-fp32, raw bits to MMA.
// Epilogue: gate math -> g_A/g_C + fused per-chunk scan summary (P,Q).
// ---------------------------------------------------------------------------
#define BK 32
#define ROWF 36                  // floats per row (32 + 4 pad); 144B rows
#define ROWB (ROWF * 4)
#define SMA (128 * ROWB)         // 18432 B
#define SMW (64 * ROWB)          // 9216 B
#define SMBUF (SMA + 2 * SMW)    // 36864 B
#define SM_BIAS (2 * SMBUF)      // 73728
#define SMTOT (SM_BIAS + 3 * 64 * 4)
// epilogue scan tiles (alias the double buffers after the mainloop)
#define EROW 68                  // 64 + 4 pad floats
#define SM_SC (128 * EROW * 4)   // sC offset = 34816

__global__ __launch_bounds__(256)
void gemm_gate(const float* __restrict__ ba,
               const float* __restrict__ bi,
               const float* __restrict__ gate) {
    extern __shared__ char smem[];
    const uint32_t sb = smem_u32(smem);
    const int tid = threadIdx.x;
    const int wid = tid >> 5;
    const int lane = tid & 31;
    const int gid = lane >> 2;       // 0..7
    const int tig = lane & 3;        // 0..3
    const int wm = wid & 3;          // M warp 0..3
    const int wn = wid >> 2;         // N warp 0..1

    const int N0 = blockIdx.x * 64;
    const int M0 = blockIdx.y * 128;

    float* bias_s = (float*)(smem + SM_BIAS);
    if (tid < 64) {
        bias_s[tid]       = ba[N0 + tid];
        bias_s[64 + tid]  = bi[N0 + tid];
        bias_s[128 + tid] = sigmoidf(gate[N0 + tid]);
    }

    auto prefetch = [&](int kt, int buf) {
        const int k0 = kt * BK;
        const uint32_t bufb = sb + buf * SMBUF;
#pragma unroll
        for (int i = 0; i < 8; i++) {
            int g = tid + i * 256;
            if (g < 1024) {
                int r = g >> 3, ch = g & 7;
                cp16(bufb + r * ROWB + ch * 16,
                     g_xr + (size_t)(M0 + r) * Dd + k0 + ch * 4);
            } else {
                int h = g - 1024;
                int p = h >> 9, r = (h >> 3) & 63, ch = h & 7;
                const float* wsrc = p ? g_wir : g_war;
                cp16(bufb + SMA + p * SMW + r * ROWB + ch * 16,
                     wsrc + (size_t)(N0 + r) * Dd + k0 + ch * 4);
            }
        }
        cp_commit();
    };

    // ldmatrix lane->row address offsets (bytes within buffer)
    const int mtx = lane >> 3;       // matrix index 0..3
    const int mrow = lane & 7;
    // A: matrices [m0-7,k0-3][m8-15,k0-3][m0-7,k4-7][m8-15,k4-7]
    const uint32_t aoff = (uint32_t)(((wm * 32 + (mtx & 1) * 8 + mrow) * ROWF +
                                      (mtx >> 1) * 4) * 4);
    // B: matrices [n0-7,k0-3][n0-7,k4-7][n8-15,k0-3][n8-15,k4-7]
    const uint32_t boff = (uint32_t)(((wn * 32 + (mtx >> 1) * 8 + mrow) * ROWF +
                                      (mtx & 1) * 4) * 4);

    float acc[2][2][4][4];           // [proj][mt][nt][c]
#pragma unroll
    for (int p = 0; p < 2; p++)
#pragma unroll
        for (int mt = 0; mt < 2; mt++)
#pragma unroll
            for (int nt = 0; nt < 4; nt++)
#pragma unroll
                for (int c = 0; c < 4; c++) acc[p][mt][nt][c] = 0.0f;

    prefetch(0, 0);

    const int NT = Dd / BK;          // 16
    for (int kt = 0; kt < NT; kt++) {
        const int buf = kt & 1;
        cp_wait0();
        __syncthreads();
        if (kt + 1 < NT) prefetch(kt + 1, buf ^ 1);

        const uint32_t Ab = sb + buf * SMBUF;
        const uint32_t Wb = Ab + SMA;

#pragma unroll
        for (int s = 0; s < 4; s++) {
            const uint32_t ks = (uint32_t)(s * 32);       // 8 floats
            uint32_t af[2][4];
#pragma unroll
            for (int mt = 0; mt < 2; mt++)
                ldsm4(af[mt], Ab + aoff + ks + (uint32_t)(mt * 16 * ROWB));
#pragma unroll
            for (int p = 0; p < 2; p++) {
                const uint32_t Wp = Wb + (uint32_t)(p * SMW);
                uint32_t braw[2][4];
#pragma unroll
                for (int ntp = 0; ntp < 2; ntp++)
                    ldsm4(braw[ntp], Wp + boff + ks + (uint32_t)(ntp * 16 * ROWB));
#pragma unroll
                for (int mt = 0; mt < 2; mt++)
#pragma unroll
                    for (int nt = 0; nt < 4; nt++) {
                        uint32_t bfr[2] = { braw[nt >> 1][(nt & 1) * 2],
                                            braw[nt >> 1][(nt & 1) * 2 + 1] };
                        mma_tf32(acc[p][mt][nt], af[mt], bfr);
                    }
            }
        }
    }
    __syncthreads();                 // mainloop done; smem buffers reusable

    // ---- gate epilogue: write g_A/g_C and stash tiles in smem ----
    float* sA = (float*)smem;                 // [128][EROW]
    float* sC = (float*)(smem + SM_SC);
#pragma unroll
    for (int mt = 0; mt < 2; mt++)
#pragma unroll
        for (int nt = 0; nt < 4; nt++)
#pragma unroll
            for (int half = 0; half < 2; half++) {
                int rl = wm * 32 + mt * 16 + gid + half * 8;     // local row
                int cl = wn * 32 + nt * 8 + tig * 2;             // local col
                float pa0 = acc[0][mt][nt][half * 2 + 0] + bias_s[cl];
                float pa1 = acc[0][mt][nt][half * 2 + 1] + bias_s[cl + 1];
                float pi0 = acc[1][mt][nt][half * 2 + 0] + bias_s[64 + cl];
                float pi1 = acc[1][mt][nt][half * 2 + 1] + bias_s[64 + cl + 1];
                float al0 = bias_s[128 + cl], al1 = bias_s[128 + cl + 1];

                float aa0 = al0 * __expf(-LN3 * sigmoidf(pa0));
                float aa1 = al1 * __expf(-LN3 * sigmoidf(pa1));
                float cv0 = sqrtf(fmaxf(1.0f - aa0 * aa0, 0.0f)) * sigmoidf(pi0) * pi0;
                float cv1 = sqrtf(fmaxf(1.0f - aa1 * aa1, 0.0f)) * sigmoidf(pi1) * pi1;

                size_t o = (size_t)(M0 + rl) * Ii + N0 + cl;
                *(float2*)&g_A[o] = make_float2(aa0, aa1);
                *(float2*)&g_C[o] = make_float2(cv0, cv1);
                sA[rl * EROW + cl] = aa0;  sA[rl * EROW + cl + 1] = aa1;
                sC[rl * EROW + cl] = cv0;  sC[rl * EROW + cl + 1] = cv1;
            }
    __syncthreads();

    // ---- fused scanA: this M-tile is exactly chunk (b, q) of 128 steps ----
    if (tid < 64) {
        const int col = tid;
        float h = 0.0f, P = 1.0f;
#pragma unroll 8
        for (int r = 0; r < 128; r++) {
            float a = sA[r * EROW + col];
            float c = sC[r * EROW + col];
            h = fmaf(a, h, c);
            P *= a;
        }
        const int b = M0 >> 11;                  // M0 / Ss
        const int q = (M0 & 2047) >> 7;          // chunk within sequence
        const int chain = b * Ii + N0 + col;
        g_P[q * NCHAIN + chain] = P;
        g_Q[q * NCHAIN + chain] = h;
    }
}

// ---------------------------------------------------------------------------
// scanB: compose chunk summaries per chain
// ---------------------------------------------------------------------------
__global__ __launch_bounds__(256)
void scanB() {
    int t = blockIdx.x * 256 + threadIdx.x;
    float carry = 0.0f;
#pragma unroll
    for (int q = 0; q < NCH; q++) {
        g_H0[q * NCHAIN + t] = carry;
        carry = fmaf(g_P[q * NCHAIN + t], carry, g_Q[q * NCHAIN + t]);
    }
}

// ---------------------------------------------------------------------------
// scanC: replay with correct carry-in
// ---------------------------------------------------------------------------
__global__ __launch_bounds__(256)
void scanC(float* __restrict__ out) {
    int t = blockIdx.x * 256 + threadIdx.x;
    int i = t & 2047;
    int rest = t >> 11;
    int b = rest & 7;
    int q = rest >> 3;
    size_t base = ((size_t)(b * Ss + q * CHS)) * Ii + i;
    float h = g_H0[q * NCHAIN + b * Ii + i];
#pragma unroll 16
    for (int s = 0; s < CHS; s++) {
        size_t idx = base + (size_t)s * Ii;
        h = fmaf(g_A[idx], h, g_C[idx]);
        out[idx] = h;
    }
}

extern "C" void kernel_launch(void* const* d_in, const int* in_sizes, int n_in,
                              void* d_out, int out_size) {
    const float* x    = (const float*)d_in[0];
    const float* Wa   = (const float*)d_in[1];
    const float* ba   = (const float*)d_in[2];
    const float* Wi   = (const float*)d_in[3];
    const float* bi   = (const float*)d_in[4];
    const float* gate = (const float*)d_in[5];
    float* out = (float*)d_out;

    float *xr, *war, *wir;
    cudaGetSymbolAddress((void**)&xr,  g_xr);
    cudaGetSymbolAddress((void**)&war, g_war);
    cudaGetSymbolAddress((void**)&wir, g_wir);

    round_tf32<<<(Mtot * Dd / 4) / 256, 256>>>(x, xr, Mtot * Dd / 4);
    round_tf32<<<(Ii * Dd / 4) / 256, 256>>>(Wa, war, Ii * Dd / 4);
    round_tf32<<<(Ii * Dd / 4) / 256, 256>>>(Wi, wir, Ii * Dd / 4);

    cudaFuncSetAttribute(gemm_gate, cudaFuncAttributeMaxDynamicSharedMemorySize, SMTOT);
    dim3 grid(Ii / 64, Mtot / 128);          // (32, 128), N fastest
    gemm_gate<<<grid, 256, SMTOT>>>(ba, bi, gate);

    scanB<<<NCHAIN / 256, 256>>>();
    scanC<<<(NCH * NCHAIN) / 256, 256>>>(out);
}